// round 1
// baseline (speedup 1.0000x reference)
#include <cuda_runtime.h>
#include <math.h>

// Problem dims (fixed by the dataset)
#define B_DIM 8192
#define I_DIM 1024
#define H_DIM 1024
#define N4    4096   // 4*H

// Scratch (device globals: allocation-free per harness rules)
__device__ float g_im   [(size_t)B_DIM * H_DIM];   // input_mapped = x@Wm + bm
__device__ float g_xmod [(size_t)B_DIM * I_DIM];   // (1+attn)*x
__device__ float g_gates[(size_t)B_DIM * N4];      // pre-LN gates

__device__ __forceinline__ float sigmoidf_(float z) {
    return 1.0f / (1.0f + __expf(-z));
}

// ---------------------------------------------------------------------------
// Classic 128x128x8 SGEMM, 256 threads, 8x8 per thread, float4 everywhere.
// C[M,N] (accum? += : =) A[M,K] @ B[K,N]  (+ bias per column if bias != null)
// All dims are multiples of tile sizes here, so no bounds checks.
// ---------------------------------------------------------------------------
__global__ __launch_bounds__(256)
void sgemm128(const float* __restrict__ A, const float* __restrict__ Bm,
              const float* __restrict__ bias, float* __restrict__ C,
              int M, int N, int K, int accum)
{
    __shared__ float As[8][128];
    __shared__ float Bs[8][128];

    const int tid  = threadIdx.x;
    const int tx   = tid & 15;       // 16 thread-cols
    const int ty   = tid >> 4;       // 16 thread-rows
    const int cRow = blockIdx.y * 128;
    const int cCol = blockIdx.x * 128;

    const int aRow = tid >> 1;            // 128 rows, 2 threads/row
    const int aCol = (tid & 1) * 4;       // 8 cols as 2x float4
    const int bRow = tid >> 5;            // 8 rows
    const int bCol = (tid & 31) * 4;      // 128 cols as float4

    const float* Aptr = A  + (size_t)(cRow + aRow) * K + aCol;
    const float* Bptr = Bm + (size_t)bRow * N + cCol + bCol;

    float acc[8][8];
#pragma unroll
    for (int i = 0; i < 8; i++)
#pragma unroll
        for (int j = 0; j < 8; j++) acc[i][j] = 0.0f;

    for (int k0 = 0; k0 < K; k0 += 8) {
        float4 av = *(const float4*)(Aptr + k0);
        As[aCol + 0][aRow] = av.x;
        As[aCol + 1][aRow] = av.y;
        As[aCol + 2][aRow] = av.z;
        As[aCol + 3][aRow] = av.w;
        float4 bv = *(const float4*)(Bptr + (size_t)k0 * N);
        *(float4*)&Bs[bRow][bCol] = bv;
        __syncthreads();

#pragma unroll
        for (int kk = 0; kk < 8; kk++) {
            float a[8], b[8];
            *(float4*)&a[0] = *(const float4*)&As[kk][ty * 8];
            *(float4*)&a[4] = *(const float4*)&As[kk][ty * 8 + 4];
            *(float4*)&b[0] = *(const float4*)&Bs[kk][tx * 8];
            *(float4*)&b[4] = *(const float4*)&Bs[kk][tx * 8 + 4];
#pragma unroll
            for (int i = 0; i < 8; i++)
#pragma unroll
                for (int j = 0; j < 8; j++)
                    acc[i][j] = fmaf(a[i], b[j], acc[i][j]);
        }
        __syncthreads();
    }

#pragma unroll
    for (int i = 0; i < 8; i++) {
        size_t row  = (size_t)(cRow + ty * 8 + i);
        float* crow = C + row * N + cCol + tx * 8;
#pragma unroll
        for (int j = 0; j < 8; j += 4) {
            float4 v = make_float4(acc[i][j], acc[i][j + 1], acc[i][j + 2], acc[i][j + 3]);
            int col = cCol + tx * 8 + j;
            if (bias) {
                v.x += bias[col]; v.y += bias[col + 1];
                v.z += bias[col + 2]; v.w += bias[col + 3];
            }
            if (accum) {
                float4 o = *(const float4*)(crow + j);
                v.x += o.x; v.y += o.y; v.z += o.z; v.w += o.w;
            }
            *(float4*)(crow + j) = v;
        }
    }
}

// ---------------------------------------------------------------------------
// Block-wide reduction of n (<=8) values simultaneously. Results in outp[0..n).
// sh must be float[32*8], outp float[8]. Safe to call back-to-back.
// ---------------------------------------------------------------------------
__device__ __forceinline__ void block_reduce(float* vals, int n,
                                             float* sh, float* outp)
{
    const int lane = threadIdx.x & 31;
    const int warp = threadIdx.x >> 5;
    const int nw   = blockDim.x >> 5;
    for (int q = 0; q < n; q++) {
        float v = vals[q];
#pragma unroll
        for (int o = 16; o > 0; o >>= 1) v += __shfl_xor_sync(0xffffffffu, v, o);
        if (lane == 0) sh[warp * 8 + q] = v;
    }
    __syncthreads();
    if (warp < n) {
        float v = (lane < nw) ? sh[lane * 8 + warp] : 0.0f;
#pragma unroll
        for (int o = 16; o > 0; o >>= 1) v += __shfl_xor_sync(0xffffffffu, v, o);
        if (lane == 0) outp[warp] = v;
    }
    __syncthreads();
}

// ---------------------------------------------------------------------------
// Per-row: attn = sigmoid(cosine_sim(input_mapped, hx)); x_mod = (1+attn)*x
// ---------------------------------------------------------------------------
__global__ __launch_bounds__(256)
void attn_scale_kernel(const float* __restrict__ x, const float* __restrict__ hx)
{
    __shared__ float sh[32 * 8];
    __shared__ float outp[8];
    const int r = blockIdx.x;
    const float* im  = g_im + (size_t)r * H_DIM;
    const float* hxr = hx   + (size_t)r * H_DIM;

    float dot = 0.0f, s1 = 0.0f, s2 = 0.0f;
    for (int j = threadIdx.x; j < H_DIM; j += 256) {
        float a = im[j], b = hxr[j];
        dot = fmaf(a, b, dot);
        s1  = fmaf(a, a, s1);
        s2  = fmaf(b, b, s2);
    }
    float vals[3] = {dot, s1, s2};
    block_reduce(vals, 3, sh, outp);

    float na = fmaxf(sqrtf(outp[1]), 1e-6f);
    float nb = fmaxf(sqrtf(outp[2]), 1e-6f);
    float attn  = sigmoidf_(outp[0] / (na * nb));
    float scale = 1.0f + attn;

    const float* xr = x + (size_t)r * I_DIM;
    float* xo = g_xmod + (size_t)r * I_DIM;
    for (int j = threadIdx.x; j < I_DIM; j += 256)
        xo[j] = xr[j] * scale;
}

// ---------------------------------------------------------------------------
// Fused epilogue, one CTA (1024 threads) per row:
//  4x LayerNorm + activations, cell update, cosine gate, both outputs.
// ---------------------------------------------------------------------------
__global__ __launch_bounds__(1024)
void epilogue_kernel(const float* __restrict__ cx,
                     const float* __restrict__ gammas,
                     const float* __restrict__ betas,
                     float* __restrict__ out)
{
    __shared__ float sh[32 * 8];
    __shared__ float outp[8];
    const int r = blockIdx.x;
    const int j = threadIdx.x;   // 0..1023
    const float* grow = g_gates + (size_t)r * N4;

    float v[4];
    v[0] = grow[j];
    v[1] = grow[j + 1024];
    v[2] = grow[j + 2048];
    v[3] = grow[j + 3072];

    float vals[8] = {v[0], v[1], v[2], v[3],
                     v[0]*v[0], v[1]*v[1], v[2]*v[2], v[3]*v[3]};
    block_reduce(vals, 8, sh, outp);

    const float invH = 1.0f / 1024.0f;
    float act[4];
#pragma unroll
    for (int q = 0; q < 4; q++) {
        float mu  = outp[q] * invH;
        float var = outp[q + 4] * invH - mu * mu;
        act[q] = (v[q] - mu) * rsqrtf(var + 1e-5f) * gammas[q * 1024 + j]
                 + betas[q * 1024 + j];
    }
    float i_g = sigmoidf_(act[0]);
    float f_g = sigmoidf_(act[1]);
    float g_g = tanhf(act[2]);
    float o_g = sigmoidf_(act[3]);

    float cxn = fmaf(f_g, cx[(size_t)r * 1024 + j], i_g * g_g);
    float hxn = o_g * tanhf(cxn);

    float vals2[3] = {hxn * cxn, hxn * hxn, cxn * cxn};
    block_reduce(vals2, 3, sh, outp);

    float na = fmaxf(sqrtf(outp[1]), 1e-6f);
    float nb = fmaxf(sqrtf(outp[2]), 1e-6f);
    float cosv = outp[0] / (na * nb);
    float gc = sigmoidf_((cosv + 1.0f) * 0.5f);

    out[(size_t)r * 1024 + j] = hxn * (1.0f + gc);
    out[(size_t)B_DIM * 1024 + (size_t)r * 1024 + j] = cxn;
}

// ---------------------------------------------------------------------------
extern "C" void kernel_launch(void* const* d_in, const int* in_sizes, int n_in,
                              void* d_out, int out_size)
{
    const float* x      = (const float*)d_in[0];
    const float* hx     = (const float*)d_in[1];
    const float* cx     = (const float*)d_in[2];
    const float* W      = (const float*)d_in[3];   // [2048, 4096]
    const float* b      = (const float*)d_in[4];   // [4096]
    const float* Wm     = (const float*)d_in[5];   // [1024, 1024]
    const float* bm     = (const float*)d_in[6];   // [1024]
    const float* gammas = (const float*)d_in[7];   // [4,1024]
    const float* betas  = (const float*)d_in[8];   // [4,1024]
    float* out = (float*)d_out;

    float *p_im, *p_xmod, *p_gates;
    cudaGetSymbolAddress((void**)&p_im,    g_im);
    cudaGetSymbolAddress((void**)&p_xmod,  g_xmod);
    cudaGetSymbolAddress((void**)&p_gates, g_gates);

    // 1) input_mapped = x @ Wm + bm        [8192,1024]
    {
        dim3 grid(H_DIM / 128, B_DIM / 128);
        sgemm128<<<grid, 256>>>(x, Wm, bm, p_im, B_DIM, H_DIM, I_DIM, 0);
    }
    // 2) attn per row; x_mod = (1+attn) * x
    attn_scale_kernel<<<B_DIM, 256>>>(x, hx);

    // 3) gates  = x_mod @ W[0:1024,:] + b   [8192,4096]
    {
        dim3 grid(N4 / 128, B_DIM / 128);
        sgemm128<<<grid, 256>>>(p_xmod, W, b, p_gates, B_DIM, N4, I_DIM, 0);
    }
    // 4) gates += hx @ W[1024:2048,:]
    {
        dim3 grid(N4 / 128, B_DIM / 128);
        sgemm128<<<grid, 256>>>(hx, W + (size_t)I_DIM * N4, nullptr, p_gates,
                                B_DIM, N4, H_DIM, 1);
    }
    // 5) fused LN + activations + cell update + cosine gate + outputs
    epilogue_kernel<<<B_DIM, 1024>>>(cx, gammas, betas, out);
}

// round 3
// speedup vs baseline: 2.5810x; 2.5810x over previous
#include <cuda_runtime.h>
#include <cuda_fp16.h>
#include <math.h>
#include <cstdint>

// Problem dims (fixed by dataset)
#define B_DIM 8192
#define I_DIM 1024
#define H_DIM 1024
#define N4    4096
#define K2    2048   // I+H

// ---------------- scratch (device globals; allocation-free) ----------------
__device__ __half g_xhi [(size_t)B_DIM * I_DIM];     // split(x)
__device__ __half g_xlo [(size_t)B_DIM * I_DIM];
__device__ __half g_ahi [(size_t)B_DIM * K2];        // [xmod | hx] split
__device__ __half g_alo [(size_t)B_DIM * K2];
__device__ __half g_wmT_hi[(size_t)H_DIM * I_DIM];   // Wm^T [H, I]
__device__ __half g_wmT_lo[(size_t)H_DIM * I_DIM];
__device__ __half g_wT_hi [(size_t)N4 * K2];         // W^T [4H, I+H]
__device__ __half g_wT_lo [(size_t)N4 * K2];
__device__ float  g_im   [(size_t)B_DIM * H_DIM];    // x@Wm + bm
__device__ float  g_gates[(size_t)B_DIM * N4];       // pre-LN gates

__device__ __forceinline__ float sigmoidf_(float z) {
    return 1.0f / (1.0f + __expf(-z));
}
__device__ __forceinline__ uint32_t smem_u32(const void* p) {
    uint32_t a;
    asm("{ .reg .u64 t; cvta.to.shared.u64 t, %1; cvt.u32.u64 %0, t; }"
        : "=r"(a) : "l"(p));
    return a;
}
// SW128-style swizzle for 128B rows: conflict-free ldmatrix + cp.async
__device__ __forceinline__ uint32_t sw128(uint32_t off) {
    return off ^ ((off >> 3) & 0x70);
}

// ---------------------------------------------------------------------------
// fp16x3-split GEMM via mma.sync.m16n8k16 (compute_103-legal HMMA path).
// C[M,N] = A @ B^T + bias (fp32 out).
// A: hi/lo fp16 [M,K] row-major.  BT: hi/lo fp16 [N,K] row-major (K-major).
// CTA tile 128x128, kc=64, 256 thr (8 warps, 2Mx4N, warp tile 64x32),
// 2-stage cp.async pipeline. Three K passes: hi*hi, hi*lo, lo*hi.
// ---------------------------------------------------------------------------
#define TM 128
#define TN 128
#define KC 64
#define STAGE_BYTES (TM * KC * 2)          // 16KB per operand tile
#define GEMM_SMEM   (4 * STAGE_BYTES)      // 2 stages x (A+B) = 64KB

__global__ __launch_bounds__(256, 2)
void hgemm_mma(const __half* __restrict__ Ahi, const __half* __restrict__ Alo,
               const __half* __restrict__ BThi, const __half* __restrict__ BTlo,
               const float* __restrict__ bias, float* __restrict__ C,
               int M, int N, int K)
{
    extern __shared__ char smem_raw[];
    const uint32_t SM_A = smem_u32(smem_raw);                  // 2 x 16KB
    const uint32_t SM_B = SM_A + 2 * STAGE_BYTES;              // 2 x 16KB

    const int tid  = threadIdx.x;
    const int wid  = tid >> 5;
    const int lane = tid & 31;
    const int wm   = (wid & 1) * 64;      // warp M offset in tile
    const int wn   = (wid >> 1) * 32;     // warp N offset in tile
    const int m0   = blockIdx.y * TM;
    const int n0   = blockIdx.x * TN;

    const int cpp = K / KC;               // chunks per split-pass
    const int nc  = 3 * cpp;
    const __half* APASS[3] = {Ahi, Ahi, Alo};
    const __half* BPASS[3] = {BThi, BTlo, BThi};

    auto load_chunk = [&](int c, int buf) {
        const int pass = c / cpp;
        const int kk   = (c - pass * cpp) * KC;
        const __half* Ag = APASS[pass] + (size_t)m0 * K + kk;
        const __half* Bg = BPASS[pass] + (size_t)n0 * K + kk;
        const uint32_t sa = SM_A + buf * STAGE_BYTES;
        const uint32_t sb = SM_B + buf * STAGE_BYTES;
#pragma unroll
        for (int t = 0; t < 4; t++) {                 // A: 1024 x 16B
            int idx = tid + 256 * t;
            int r = idx >> 3, i = idx & 7;
            uint32_t d = sa + sw128((uint32_t)(r * 128 + i * 16));
            const void* g = Ag + (size_t)r * K + i * 8;
            asm volatile("cp.async.cg.shared.global [%0], [%1], 16;" :: "r"(d), "l"(g));
        }
#pragma unroll
        for (int t = 0; t < 4; t++) {                 // B: 1024 x 16B
            int idx = tid + 256 * t;
            int r = idx >> 3, i = idx & 7;
            uint32_t d = sb + sw128((uint32_t)(r * 128 + i * 16));
            const void* g = Bg + (size_t)r * K + i * 8;
            asm volatile("cp.async.cg.shared.global [%0], [%1], 16;" :: "r"(d), "l"(g));
        }
        asm volatile("cp.async.commit_group;" ::: "memory");
    };

    float acc[4][4][4];
#pragma unroll
    for (int mi = 0; mi < 4; mi++)
#pragma unroll
        for (int ni = 0; ni < 4; ni++)
#pragma unroll
            for (int q = 0; q < 4; q++) acc[mi][ni][q] = 0.0f;

    load_chunk(0, 0);
    load_chunk(1, 1);

    // ldmatrix lane address components (constant across chunks)
    const int aRow = wm + (lane & 15);            // + mi*16
    const int aColB = (lane >> 4) * 16;           // byte offset of k-half
    const int bRow = wn + (lane & 7);             // + ni*8
    const int bColB = ((lane >> 3) & 1) * 16;

    for (int c = 0; c < nc; c++) {
        const int buf = c & 1;
        if (c + 1 < nc) asm volatile("cp.async.wait_group 1;" ::: "memory");
        else            asm volatile("cp.async.wait_group 0;" ::: "memory");
        __syncthreads();

        const uint32_t sa = SM_A + buf * STAGE_BYTES;
        const uint32_t sb = SM_B + buf * STAGE_BYTES;

#pragma unroll
        for (int ks = 0; ks < KC / 16; ks++) {
            uint32_t a[4][4], b[4][2];
#pragma unroll
            for (int mi = 0; mi < 4; mi++) {
                uint32_t addr = sa + sw128((uint32_t)((aRow + mi * 16) * 128 + ks * 32 + aColB));
                asm volatile("ldmatrix.sync.aligned.m8n8.x4.shared.b16 {%0,%1,%2,%3}, [%4];"
                             : "=r"(a[mi][0]), "=r"(a[mi][1]), "=r"(a[mi][2]), "=r"(a[mi][3])
                             : "r"(addr));
            }
#pragma unroll
            for (int ni = 0; ni < 4; ni++) {
                uint32_t addr = sb + sw128((uint32_t)((bRow + ni * 8) * 128 + ks * 32 + bColB));
                asm volatile("ldmatrix.sync.aligned.m8n8.x2.shared.b16 {%0,%1}, [%2];"
                             : "=r"(b[ni][0]), "=r"(b[ni][1]) : "r"(addr));
            }
#pragma unroll
            for (int mi = 0; mi < 4; mi++)
#pragma unroll
                for (int ni = 0; ni < 4; ni++) {
                    asm volatile(
                        "mma.sync.aligned.m16n8k16.row.col.f32.f16.f16.f32 "
                        "{%0,%1,%2,%3}, {%4,%5,%6,%7}, {%8,%9}, {%0,%1,%2,%3};"
                        : "+f"(acc[mi][ni][0]), "+f"(acc[mi][ni][1]),
                          "+f"(acc[mi][ni][2]), "+f"(acc[mi][ni][3])
                        : "r"(a[mi][0]), "r"(a[mi][1]), "r"(a[mi][2]), "r"(a[mi][3]),
                          "r"(b[ni][0]), "r"(b[ni][1]));
                }
        }
        __syncthreads();
        if (c + 2 < nc) load_chunk(c + 2, buf);
    }

    // Store: lane l owns (row = mi*16 + l/4 (+8), col = ni*8 + (l%4)*2)
    const int r0 = m0 + wm + (lane >> 2);
    const int c0 = n0 + wn + (lane & 3) * 2;
#pragma unroll
    for (int mi = 0; mi < 4; mi++) {
#pragma unroll
        for (int ni = 0; ni < 4; ni++) {
            int col = c0 + ni * 8;
            float bx = bias[col], by = bias[col + 1];
            float2 v0 = make_float2(acc[mi][ni][0] + bx, acc[mi][ni][1] + by);
            float2 v1 = make_float2(acc[mi][ni][2] + bx, acc[mi][ni][3] + by);
            *(float2*)(C + (size_t)(r0 + mi * 16) * N + col) = v0;
            *(float2*)(C + (size_t)(r0 + mi * 16 + 8) * N + col) = v1;
        }
    }
}

// ---------------------------------------------------------------------------
// Transpose + fp16 split: D[c][r] = split(S[r][c]);  S:[R,C] f32, D:[C,R] f16
// ---------------------------------------------------------------------------
__global__ __launch_bounds__(256)
void transpose_split(const float* __restrict__ S, __half* __restrict__ Dhi,
                     __half* __restrict__ Dlo, int R, int C)
{
    __shared__ float t[32][33];
    const int c0 = blockIdx.x * 32, r0 = blockIdx.y * 32;
    const int tx = threadIdx.x, ty = threadIdx.y;   // 32 x 8
    for (int i = ty; i < 32; i += 8)
        t[i][tx] = S[(size_t)(r0 + i) * C + c0 + tx];
    __syncthreads();
    for (int j = ty; j < 32; j += 8) {
        float v = t[tx][j];                          // S[r0+tx][c0+j]
        __half h = __float2half_rn(v);
        __half l = __float2half_rn(v - __half2float(h));
        size_t o = (size_t)(c0 + j) * R + r0 + tx;
        Dhi[o] = h; Dlo[o] = l;
    }
}

// fp16 split, row layout preserved (optional dst column offset / stride)
__global__ __launch_bounds__(256)
void split_rows(const float* __restrict__ S, __half* __restrict__ Dhi,
                __half* __restrict__ Dlo, int total, int cols, int dstride, int coff)
{
    for (int idx = blockIdx.x * blockDim.x + threadIdx.x; idx < total;
         idx += gridDim.x * blockDim.x) {
        int r = idx / cols, c = idx - r * cols;
        float v = S[idx];
        __half h = __float2half_rn(v);
        __half l = __float2half_rn(v - __half2float(h));
        size_t o = (size_t)r * dstride + coff + c;
        Dhi[o] = h; Dlo[o] = l;
    }
}

// ---------------------------------------------------------------------------
__device__ __forceinline__ void block_reduce(float* vals, int n, float* sh, float* outp)
{
    const int lane = threadIdx.x & 31;
    const int warp = threadIdx.x >> 5;
    const int nw   = blockDim.x >> 5;
    for (int q = 0; q < n; q++) {
        float v = vals[q];
#pragma unroll
        for (int o = 16; o > 0; o >>= 1) v += __shfl_xor_sync(0xffffffffu, v, o);
        if (lane == 0) sh[warp * 8 + q] = v;
    }
    __syncthreads();
    if (warp < n) {
        float v = (lane < nw) ? sh[lane * 8 + warp] : 0.0f;
#pragma unroll
        for (int o = 16; o > 0; o >>= 1) v += __shfl_xor_sync(0xffffffffu, v, o);
        if (lane == 0) outp[warp] = v;
    }
    __syncthreads();
}

// ---------------------------------------------------------------------------
// attn = sigmoid(cos(im, hx)); write split((1+attn)*x) into A cols [0,1024)
// ---------------------------------------------------------------------------
__global__ __launch_bounds__(256)
void attn_scale_kernel(const float* __restrict__ x, const float* __restrict__ hx)
{
    __shared__ float sh[32 * 8];
    __shared__ float outp[8];
    const int r = blockIdx.x;
    const float* im  = g_im + (size_t)r * H_DIM;
    const float* hxr = hx   + (size_t)r * H_DIM;

    float dot = 0.0f, s1 = 0.0f, s2 = 0.0f;
    for (int j = threadIdx.x; j < H_DIM; j += 256) {
        float a = im[j], b = hxr[j];
        dot = fmaf(a, b, dot);
        s1  = fmaf(a, a, s1);
        s2  = fmaf(b, b, s2);
    }
    float vals[3] = {dot, s1, s2};
    block_reduce(vals, 3, sh, outp);

    float na = fmaxf(sqrtf(outp[1]), 1e-6f);
    float nb = fmaxf(sqrtf(outp[2]), 1e-6f);
    float scale = 1.0f + sigmoidf_(outp[0] / (na * nb));

    const float* xr = x + (size_t)r * I_DIM;
    __half* dh = g_ahi + (size_t)r * K2;
    __half* dl = g_alo + (size_t)r * K2;
    for (int j = threadIdx.x; j < I_DIM; j += 256) {
        float v = xr[j] * scale;
        __half h = __float2half_rn(v);
        dh[j] = h;
        dl[j] = __float2half_rn(v - __half2float(h));
    }
}

// ---------------------------------------------------------------------------
// Fused epilogue: 4x LN + act, cell update, cosine gate, outputs
// ---------------------------------------------------------------------------
__global__ __launch_bounds__(1024)
void epilogue_kernel(const float* __restrict__ cx, const float* __restrict__ gammas,
                     const float* __restrict__ betas, float* __restrict__ out)
{
    __shared__ float sh[32 * 8];
    __shared__ float outp[8];
    const int r = blockIdx.x;
    const int j = threadIdx.x;
    const float* grow = g_gates + (size_t)r * N4;

    float v[4];
    v[0] = grow[j];
    v[1] = grow[j + 1024];
    v[2] = grow[j + 2048];
    v[3] = grow[j + 3072];

    float vals[8] = {v[0], v[1], v[2], v[3],
                     v[0]*v[0], v[1]*v[1], v[2]*v[2], v[3]*v[3]};
    block_reduce(vals, 8, sh, outp);

    const float invH = 1.0f / 1024.0f;
    float act[4];
#pragma unroll
    for (int q = 0; q < 4; q++) {
        float mu  = outp[q] * invH;
        float var = outp[q + 4] * invH - mu * mu;
        act[q] = (v[q] - mu) * rsqrtf(var + 1e-5f) * gammas[q * 1024 + j]
                 + betas[q * 1024 + j];
    }
    float i_g = sigmoidf_(act[0]);
    float f_g = sigmoidf_(act[1]);
    float g_g = tanhf(act[2]);
    float o_g = sigmoidf_(act[3]);

    float cxn = fmaf(f_g, cx[(size_t)r * 1024 + j], i_g * g_g);
    float hxn = o_g * tanhf(cxn);

    float vals2[3] = {hxn * cxn, hxn * hxn, cxn * cxn};
    block_reduce(vals2, 3, sh, outp);

    float na = fmaxf(sqrtf(outp[1]), 1e-6f);
    float nb = fmaxf(sqrtf(outp[2]), 1e-6f);
    float gc = sigmoidf_((outp[0] / (na * nb) + 1.0f) * 0.5f);

    out[(size_t)r * 1024 + j] = hxn * (1.0f + gc);
    out[(size_t)B_DIM * 1024 + (size_t)r * 1024 + j] = cxn;
}

// ---------------------------------------------------------------------------
extern "C" void kernel_launch(void* const* d_in, const int* in_sizes, int n_in,
                              void* d_out, int out_size)
{
    const float* x      = (const float*)d_in[0];
    const float* hx     = (const float*)d_in[1];
    const float* cx     = (const float*)d_in[2];
    const float* W      = (const float*)d_in[3];   // [2048, 4096]
    const float* b      = (const float*)d_in[4];   // [4096]
    const float* Wm     = (const float*)d_in[5];   // [1024, 1024]
    const float* bm     = (const float*)d_in[6];   // [1024]
    const float* gammas = (const float*)d_in[7];
    const float* betas  = (const float*)d_in[8];
    float* out = (float*)d_out;

    __half *p_xhi, *p_xlo, *p_ahi, *p_alo, *p_wmThi, *p_wmTlo, *p_wThi, *p_wTlo;
    float *p_im, *p_gates;
    cudaGetSymbolAddress((void**)&p_xhi,   g_xhi);
    cudaGetSymbolAddress((void**)&p_xlo,   g_xlo);
    cudaGetSymbolAddress((void**)&p_ahi,   g_ahi);
    cudaGetSymbolAddress((void**)&p_alo,   g_alo);
    cudaGetSymbolAddress((void**)&p_wmThi, g_wmT_hi);
    cudaGetSymbolAddress((void**)&p_wmTlo, g_wmT_lo);
    cudaGetSymbolAddress((void**)&p_wThi,  g_wT_hi);
    cudaGetSymbolAddress((void**)&p_wTlo,  g_wT_lo);
    cudaGetSymbolAddress((void**)&p_im,    g_im);
    cudaGetSymbolAddress((void**)&p_gates, g_gates);

    cudaFuncSetAttribute(hgemm_mma, cudaFuncAttributeMaxDynamicSharedMemorySize,
                         GEMM_SMEM);

    // 1) weight transpose + fp16 split
    transpose_split<<<dim3(H_DIM / 32, I_DIM / 32), dim3(32, 8)>>>(Wm, p_wmThi, p_wmTlo, I_DIM, H_DIM);
    transpose_split<<<dim3(N4 / 32, K2 / 32), dim3(32, 8)>>>(W, p_wThi, p_wTlo, K2, N4);

    // 2) split activations
    split_rows<<<4096, 256>>>(x,  p_xhi, p_xlo, B_DIM * I_DIM, I_DIM, I_DIM, 0);
    split_rows<<<4096, 256>>>(hx, p_ahi, p_alo, B_DIM * H_DIM, H_DIM, K2, I_DIM);

    // 3) GEMM1: im = x @ Wm + bm     [8192,1024]
    hgemm_mma<<<dim3(H_DIM / TN, B_DIM / TM), 256, GEMM_SMEM>>>(
        p_xhi, p_xlo, p_wmThi, p_wmTlo, bm, p_im, B_DIM, H_DIM, I_DIM);

    // 4) attn gate; write split x_mod into A cols [0,1024)
    attn_scale_kernel<<<B_DIM, 256>>>(x, hx);

    // 5) GEMM2: gates = [xmod|hx] @ W + b   [8192,4096], K=2048
    hgemm_mma<<<dim3(N4 / TN, B_DIM / TM), 256, GEMM_SMEM>>>(
        p_ahi, p_alo, p_wThi, p_wTlo, b, p_gates, B_DIM, N4, K2);

    // 6) fused LN/activation/cell/cosine epilogue
    epilogue_kernel<<<B_DIM, 1024>>>(cx, gammas, betas, out);
}